// round 1
// baseline (speedup 1.0000x reference)
#include <cuda_runtime.h>
#include <cstdint>

#define L_SEQ 2048
#define BATCH 8
#define EMB   1024
#define MTOT  (BATCH * L_SEQ)   // 16384

// ---------------- scratch (device globals: no allocations allowed) ----------
__device__ float g_v[(size_t)MTOT * EMB];    // 64 MB: value projection
__device__ float g_att[(size_t)MTOT * EMB];  // 64 MB: attended values
__device__ float g_cst[BATCH * 2 * 128];     // per-batch 'first'/'last' head vectors

// head position codes: 0=center 1=left 2=right 3=first 4=last
__constant__ int c_pos[8] = {0, 1, 2, 3, 4, 0, 1, 2};

// exp(-d^2/2) for d = 0..7 (double-accurate literals)
__constant__ float c_wtab[8] = {
    1.0f,
    0.60653065971263342f,
    0.13533528323661270f,
    0.011108996538242306f,
    3.3546262790251185e-4f,
    3.7266531720786709e-6f,
    1.5229979744712628e-8f,
    2.2897348456455531e-11f
};

// ---------------------------------------------------------------------------
// NT SGEMM: C[M,N] = A[M,K] * B[N,K]^T   (both row-major, K contiguous)
// 128x128 block tile, BK=16, 8x8 per-thread microtile, 256 threads.
// ---------------------------------------------------------------------------
__global__ __launch_bounds__(256)
void sgemm_nt(const float* __restrict__ A, const float* __restrict__ B,
              float* __restrict__ C, int M, int N, int K)
{
    __shared__ float As[16][132];   // [k][m], +4 pad to spread banks
    __shared__ float Bs[16][132];   // [k][n]

    const int tid = threadIdx.x;
    const int tx  = tid & 15;       // N direction (0..15)
    const int ty  = tid >> 4;       // M direction (0..15)

    const float* Ab = A + (size_t)blockIdx.y * 128 * K;
    const float* Bb = B + (size_t)blockIdx.x * 128 * K;

    float acc[8][8];
#pragma unroll
    for (int i = 0; i < 8; ++i)
#pragma unroll
        for (int j = 0; j < 8; ++j) acc[i][j] = 0.f;

    const int lrow = tid >> 2;         // 0..63
    const int lc4  = (tid & 3) << 2;   // 0,4,8,12

    for (int k0 = 0; k0 < K; k0 += 16) {
#pragma unroll
        for (int i = 0; i < 2; ++i) {
            const int row = lrow + i * 64;
            float4 va = *(const float4*)(Ab + (size_t)row * K + k0 + lc4);
            As[lc4 + 0][row] = va.x;
            As[lc4 + 1][row] = va.y;
            As[lc4 + 2][row] = va.z;
            As[lc4 + 3][row] = va.w;
            float4 vb = *(const float4*)(Bb + (size_t)row * K + k0 + lc4);
            Bs[lc4 + 0][row] = vb.x;
            Bs[lc4 + 1][row] = vb.y;
            Bs[lc4 + 2][row] = vb.z;
            Bs[lc4 + 3][row] = vb.w;
        }
        __syncthreads();

#pragma unroll
        for (int kk = 0; kk < 16; ++kk) {
            float4 a0 = *(const float4*)&As[kk][ty * 8];
            float4 a1 = *(const float4*)&As[kk][ty * 8 + 4];
            float4 b0 = *(const float4*)&Bs[kk][tx * 8];
            float4 b1 = *(const float4*)&Bs[kk][tx * 8 + 4];
            float ar[8] = {a0.x, a0.y, a0.z, a0.w, a1.x, a1.y, a1.z, a1.w};
            float br[8] = {b0.x, b0.y, b0.z, b0.w, b1.x, b1.y, b1.z, b1.w};
#pragma unroll
            for (int i = 0; i < 8; ++i)
#pragma unroll
                for (int j = 0; j < 8; ++j)
                    acc[i][j] += ar[i] * br[j];
        }
        __syncthreads();
    }

    float* Cb = C + (size_t)(blockIdx.y * 128 + ty * 8) * N + blockIdx.x * 128 + tx * 8;
#pragma unroll
    for (int i = 0; i < 8; ++i) {
        *(float4*)(Cb + (size_t)i * N)     = make_float4(acc[i][0], acc[i][1], acc[i][2], acc[i][3]);
        *(float4*)(Cb + (size_t)i * N + 4) = make_float4(acc[i][4], acc[i][5], acc[i][6], acc[i][7]);
    }
}

// ---------------------------------------------------------------------------
// Query-independent heads: 'first' (h=3) and 'last' (h=4).
// out[b, p] = sum_j w_j * v[b, k_j, h*128 + p] / Z  (one-sided window)
// ---------------------------------------------------------------------------
__global__ void attn_const_kernel(const float* __restrict__ v, float* __restrict__ cst)
{
    const int b     = blockIdx.x;
    const int which = blockIdx.y;           // 0 = first (h=3), 1 = last (h=4)
    const int p     = threadIdx.x;          // 0..127
    const int h     = which ? 4 : 3;

    float Z = 0.f, acc = 0.f;
#pragma unroll
    for (int j = 0; j < 8; ++j) {
        const int   k = which ? (L_SEQ - 1 - j) : j;
        const float w = c_wtab[j];
        Z   += w;
        acc += w * v[((size_t)b * L_SEQ + k) * EMB + h * 128 + p];
    }
    cst[(b * 2 + which) * 128 + p] = acc / Z;
}

// ---------------------------------------------------------------------------
// Banded Gaussian "attention": for center/left/right heads, a 15-tap conv
// over the sequence dim (boundary-aware softmax normalization). Tiled:
// 16 queries x 256 columns per block, 32-row value stage in smem.
// ---------------------------------------------------------------------------
#define QT 16
#define CT 256
#define KT 32

__global__ __launch_bounds__(256)
void attn_kernel(const float* __restrict__ v, float* __restrict__ att,
                 const float* __restrict__ cst)
{
    const int b   = blockIdx.z;
    const int q0  = blockIdx.y * QT;
    const int c0  = blockIdx.x * CT;
    const int tid = threadIdx.x;

    __shared__ float vt[KT][CT];

    const float* vb = v + (size_t)b * L_SEQ * EMB;
#pragma unroll
    for (int i = 0; i < 8; ++i) {
        const int id = tid + i * 256;        // 0..2047
        const int kb = id >> 6;              // 0..31
        const int cc = (id & 63) << 2;       // col*4
        const int k  = q0 - 8 + kb;
        float4 val = make_float4(0.f, 0.f, 0.f, 0.f);
        if (k >= 0 && k < L_SEQ)
            val = *(const float4*)(vb + (size_t)k * EMB + c0 + cc);
        *(float4*)&vt[kb][cc] = val;
    }
    __syncthreads();

    const int c   = c0 + tid;
    const int h   = c >> 7;
    const int pos = c_pos[h];
    float* ob = att + ((size_t)b * L_SEQ + q0) * EMB + c;

    if (pos <= 2) {
        const int off = (pos == 0) ? 0 : (pos == 1 ? -1 : 1);
#pragma unroll
        for (int qq = 0; qq < QT; ++qq) {
            const int cen = q0 + qq + off;
            const int k0  = max(0, cen - 7);
            const int k1  = min(L_SEQ - 1, cen + 7);
            float Z = 0.f, acc = 0.f;
            for (int k = k0; k <= k1; ++k) {
                const int   d = k - cen;
                const float w = c_wtab[d < 0 ? -d : d];
                Z   += w;
                acc += w * vt[k - q0 + 8][tid];
            }
            ob[(size_t)qq * EMB] = acc / Z;
        }
    } else {
        const float val = cst[(b * 2 + (pos == 4)) * 128 + (c & 127)];
#pragma unroll
        for (int qq = 0; qq < QT; ++qq)
            ob[(size_t)qq * EMB] = val;
    }
}

// ---------------------------------------------------------------------------
extern "C" void kernel_launch(void* const* d_in, const int* in_sizes, int n_in,
                              void* d_out, int out_size)
{
    const float* x     = (const float*)d_in[0];
    const float* W_in  = (const float*)d_in[1];
    const float* W_out = (const float*)d_in[2];
    float* out = (float*)d_out;

    float *v, *att, *cst;
    cudaGetSymbolAddress((void**)&v,   g_v);
    cudaGetSymbolAddress((void**)&att, g_att);
    cudaGetSymbolAddress((void**)&cst, g_cst);

    const dim3 gemm_grid(EMB / 128, MTOT / 128);

    // 1) v = x @ W_in^T
    sgemm_nt<<<gemm_grid, 256>>>(x, W_in, v, MTOT, EMB, EMB);
    // 2a) constant heads ('first'/'last')
    attn_const_kernel<<<dim3(BATCH, 2), 128>>>(v, cst);
    // 2b) banded Gaussian attention
    attn_kernel<<<dim3(EMB / CT, L_SEQ / QT, BATCH), 256>>>(v, att, cst);
    // 3) out = att @ W_out^T
    sgemm_nt<<<gemm_grid, 256>>>(att, W_out, out, MTOT, EMB, EMB);
}

// round 3
// speedup vs baseline: 1.1595x; 1.1595x over previous
#include <cuda_runtime.h>
#include <cuda_bf16.h>
#include <cstdint>

#define L_SEQ 2048
#define BATCH 8
#define EMB   1024
#define KDIM  1024
#define MTOT  (BATCH * L_SEQ)   // 16384

// ---- GEMM tiling ----
#define BM 128
#define BN 128
#define BK 16
#define NCHUNK (KDIM / BK)      // 64
#define GTHREADS 256

// smem: rows padded to 48B (32B data + 16B pad) -> 20-word stride is a
// perfect bank permutation mod 32: conflict-free ldmatrix, no swizzle.
#define RSTRIDE 48
#define MAT_BYTES (BM * RSTRIDE)            // 6144
#define STAGE_BYTES (4 * MAT_BYTES)         // 24576 (Ah, Al, Bh, Bl)
#define SMEM_BYTES (2 * STAGE_BYTES)        // 49152 = 48KB exactly

// ---------------- scratch (device globals) ----------------
__device__ __nv_bfloat16 g_xhi[(size_t)MTOT * KDIM];
__device__ __nv_bfloat16 g_xlo[(size_t)MTOT * KDIM];
__device__ __nv_bfloat16 g_wihi[(size_t)EMB * KDIM];
__device__ __nv_bfloat16 g_wilo[(size_t)EMB * KDIM];
__device__ __nv_bfloat16 g_wohi[(size_t)EMB * KDIM];
__device__ __nv_bfloat16 g_wolo[(size_t)EMB * KDIM];
__device__ float         g_v[(size_t)MTOT * EMB];
__device__ __nv_bfloat16 g_atthi[(size_t)MTOT * EMB];
__device__ __nv_bfloat16 g_attlo[(size_t)MTOT * EMB];
__device__ float         g_cst[BATCH * 2 * 128];

__constant__ int c_pos[8] = {0, 1, 2, 3, 4, 0, 1, 2};
__constant__ float c_wtab[8] = {
    1.0f, 0.60653065971263342f, 0.13533528323661270f, 0.011108996538242306f,
    3.3546262790251185e-4f, 3.7266531720786709e-6f, 1.5229979744712628e-8f,
    2.2897348456455531e-11f
};

// ---------------- PTX helpers ----------------
__device__ __forceinline__ uint32_t smem_u32(const void* p) {
    uint32_t a;
    asm("{ .reg .u64 t; cvta.to.shared.u64 t, %1; cvt.u32.u64 %0, t; }" : "=r"(a) : "l"(p));
    return a;
}
__device__ __forceinline__ void cp16(uint32_t dst, const void* src) {
    asm volatile("cp.async.cg.shared.global [%0], [%1], 16;" :: "r"(dst), "l"(src) : "memory");
}
__device__ __forceinline__ void cp_commit() { asm volatile("cp.async.commit_group;" ::: "memory"); }
__device__ __forceinline__ void cp_wait1()  { asm volatile("cp.async.wait_group 1;" ::: "memory"); }
__device__ __forceinline__ void cp_wait0()  { asm volatile("cp.async.wait_group 0;" ::: "memory"); }

__device__ __forceinline__ void ldx4(uint32_t* r, uint32_t addr) {
    asm volatile("ldmatrix.sync.aligned.m8n8.x4.shared.b16 {%0,%1,%2,%3}, [%4];"
                 : "=r"(r[0]), "=r"(r[1]), "=r"(r[2]), "=r"(r[3]) : "r"(addr));
}
__device__ __forceinline__ void mma16816(float* c, const uint32_t* a, const uint32_t* b) {
    asm volatile("mma.sync.aligned.m16n8k16.row.col.f32.bf16.bf16.f32 "
                 "{%0,%1,%2,%3}, {%4,%5,%6,%7}, {%8,%9}, {%0,%1,%2,%3};"
                 : "+f"(c[0]), "+f"(c[1]), "+f"(c[2]), "+f"(c[3])
                 : "r"(a[0]), "r"(a[1]), "r"(a[2]), "r"(a[3]), "r"(b[0]), "r"(b[1]));
}

// ---------------------------------------------------------------------------
// bf16x3 mma.sync GEMM:  C[M,N](f32) = (Ah+Al)[M,K] · (Bh+Bl)[N,K]^T
// ---------------------------------------------------------------------------
__device__ __forceinline__ void load_chunk(
    uint32_t sb, int stage, int k0, int row0, int col0,
    const __nv_bfloat16* __restrict__ Ah, const __nv_bfloat16* __restrict__ Al,
    const __nv_bfloat16* __restrict__ Bh, const __nv_bfloat16* __restrict__ Bl, int tid)
{
    const int r = tid >> 1, c = tid & 1;                // 128 rows x 2 16B-chunks
    const uint32_t st = sb + stage * STAGE_BYTES + r * RSTRIDE + c * 16;
    const size_t ga = (size_t)(row0 + r) * KDIM + k0 + c * 8;
    const size_t gb = (size_t)(col0 + r) * KDIM + k0 + c * 8;
    cp16(st,                 Ah + ga);
    cp16(st + MAT_BYTES,     Al + ga);
    cp16(st + 2 * MAT_BYTES, Bh + gb);
    cp16(st + 3 * MAT_BYTES, Bl + gb);
    cp_commit();
}

__global__ __launch_bounds__(GTHREADS, 1)
void gemm_bf16x3(const __nv_bfloat16* __restrict__ Ah, const __nv_bfloat16* __restrict__ Al,
                 const __nv_bfloat16* __restrict__ Bh, const __nv_bfloat16* __restrict__ Bl,
                 float* __restrict__ C)
{
    __shared__ char smem[SMEM_BYTES];
    const uint32_t sb = smem_u32(smem);
    const int tid  = threadIdx.x;
    const int lane = tid & 31, wid = tid >> 5;
    const int wm = (wid & 1) * 64, wn = (wid >> 1) * 32;
    const int row0 = blockIdx.y * BM, col0 = blockIdx.x * BN;

    float acc[4][4][4];
#pragma unroll
    for (int i = 0; i < 4; ++i)
#pragma unroll
        for (int j = 0; j < 4; ++j)
#pragma unroll
            for (int k = 0; k < 4; ++k) acc[i][j][k] = 0.f;

    // per-lane ldmatrix source offsets (within a matrix block)
    const uint32_t a_off = (wm + (lane & 15)) * RSTRIDE + ((lane >> 4) << 4);
    const uint32_t b_off = (wn + (lane & 15)) * RSTRIDE + ((lane >> 4) << 4);

    load_chunk(sb, 0, 0, row0, col0, Ah, Al, Bh, Bl, tid);

    for (int i = 0; i < NCHUNK; ++i) {
        if (i + 1 < NCHUNK) {
            load_chunk(sb, (i + 1) & 1, (i + 1) * BK, row0, col0, Ah, Al, Bh, Bl, tid);
            cp_wait1();
        } else {
            cp_wait0();
        }
        __syncthreads();

        const uint32_t st = sb + (i & 1) * STAGE_BYTES;

        uint32_t ah[4][4], al[4][4];
#pragma unroll
        for (int t = 0; t < 4; ++t) {
            const uint32_t addr = st + a_off + t * (16 * RSTRIDE);
            ldx4(ah[t], addr);
            ldx4(al[t], addr + MAT_BYTES);
        }
        uint32_t bh[4][2], bl[4][2];
#pragma unroll
        for (int p = 0; p < 2; ++p) {
            const uint32_t addr = st + 2 * MAT_BYTES + b_off + p * (16 * RSTRIDE);
            uint32_t r[4];
            ldx4(r, addr);
            bh[2*p][0] = r[0]; bh[2*p][1] = r[2]; bh[2*p+1][0] = r[1]; bh[2*p+1][1] = r[3];
            ldx4(r, addr + MAT_BYTES);
            bl[2*p][0] = r[0]; bl[2*p][1] = r[2]; bl[2*p+1][0] = r[1]; bl[2*p+1][1] = r[3];
        }

#pragma unroll
        for (int mt = 0; mt < 4; ++mt)
#pragma unroll
            for (int nt = 0; nt < 4; ++nt) {
                mma16816(acc[mt][nt], ah[mt], bh[nt]);
                mma16816(acc[mt][nt], ah[mt], bl[nt]);
                mma16816(acc[mt][nt], al[mt], bh[nt]);
            }
        __syncthreads();
    }

    // epilogue: fp32 direct store
#pragma unroll
    for (int mt = 0; mt < 4; ++mt) {
        const int m = row0 + wm + mt * 16 + (lane >> 2);
#pragma unroll
        for (int nt = 0; nt < 4; ++nt) {
            const int n = col0 + wn + nt * 8 + (lane & 3) * 2;
            *(float2*)(C + (size_t)m * EMB + n)       = make_float2(acc[mt][nt][0], acc[mt][nt][1]);
            *(float2*)(C + (size_t)(m + 8) * EMB + n) = make_float2(acc[mt][nt][2], acc[mt][nt][3]);
        }
    }
}

// ---------------------------------------------------------------------------
// fp32 -> bf16 hi/lo split
// ---------------------------------------------------------------------------
__global__ __launch_bounds__(256)
void split_kernel(const float* __restrict__ src, __nv_bfloat16* __restrict__ hi,
                  __nv_bfloat16* __restrict__ lo, int n)
{
    int i = (blockIdx.x * 256 + threadIdx.x) * 4;
    if (i >= n) return;
    float4 v = *(const float4*)(src + i);
    float f[4] = {v.x, v.y, v.z, v.w};
    __nv_bfloat16 h[4], l[4];
#pragma unroll
    for (int j = 0; j < 4; ++j) {
        h[j] = __float2bfloat16(f[j]);
        l[j] = __float2bfloat16(f[j] - __bfloat162float(h[j]));
    }
    *(uint2*)(hi + i) = *(uint2*)h;
    *(uint2*)(lo + i) = *(uint2*)l;
}

// ---------------------------------------------------------------------------
// attention: banded Gaussian conv + constant heads; emits bf16 hi/lo
// ---------------------------------------------------------------------------
__global__ void attn_const_kernel(const float* __restrict__ v, float* __restrict__ cst)
{
    const int b = blockIdx.x, which = blockIdx.y, p = threadIdx.x;
    const int h = which ? 4 : 3;
    float Z = 0.f, acc = 0.f;
#pragma unroll
    for (int j = 0; j < 8; ++j) {
        const int   k = which ? (L_SEQ - 1 - j) : j;
        const float w = c_wtab[j];
        Z += w;
        acc += w * v[((size_t)b * L_SEQ + k) * EMB + h * 128 + p];
    }
    cst[(b * 2 + which) * 128 + p] = acc / Z;
}

#define QT 16
#define CT 256
#define KT 32

__global__ __launch_bounds__(256)
void attn_kernel(const float* __restrict__ v, __nv_bfloat16* __restrict__ ahi,
                 __nv_bfloat16* __restrict__ alo, const float* __restrict__ cst)
{
    const int b = blockIdx.z, q0 = blockIdx.y * QT, c0 = blockIdx.x * CT;
    const int tid = threadIdx.x;
    __shared__ float vt[KT][CT];

    const float* vb = v + (size_t)b * L_SEQ * EMB;
#pragma unroll
    for (int i = 0; i < 8; ++i) {
        const int id = tid + i * 256;
        const int kb = id >> 6, cc = (id & 63) << 2;
        const int k  = q0 - 8 + kb;
        float4 val = make_float4(0.f, 0.f, 0.f, 0.f);
        if (k >= 0 && k < L_SEQ) val = *(const float4*)(vb + (size_t)k * EMB + c0 + cc);
        *(float4*)&vt[kb][cc] = val;
    }
    __syncthreads();

    const int c = c0 + tid, h = c >> 7, pos = c_pos[h];
    const size_t obase = ((size_t)b * L_SEQ + q0) * EMB + c;

    if (pos <= 2) {
        const int off = (pos == 0) ? 0 : (pos == 1 ? -1 : 1);
#pragma unroll
        for (int qq = 0; qq < QT; ++qq) {
            const int cen = q0 + qq + off;
            const int k0 = max(0, cen - 7), k1 = min(L_SEQ - 1, cen + 7);
            float Z = 0.f, acc = 0.f;
            for (int k = k0; k <= k1; ++k) {
                const int   d = k - cen;
                const float w = c_wtab[d < 0 ? -d : d];
                Z += w;
                acc += w * vt[k - q0 + 8][tid];
            }
            const float r = acc / Z;
            __nv_bfloat16 hh = __float2bfloat16(r);
            ahi[obase + (size_t)qq * EMB] = hh;
            alo[obase + (size_t)qq * EMB] = __float2bfloat16(r - __bfloat162float(hh));
        }
    } else {
        const float r = cst[(b * 2 + (pos == 4)) * 128 + (c & 127)];
        __nv_bfloat16 hh = __float2bfloat16(r);
        __nv_bfloat16 ll = __float2bfloat16(r - __bfloat162float(hh));
#pragma unroll
        for (int qq = 0; qq < QT; ++qq) {
            ahi[obase + (size_t)qq * EMB] = hh;
            alo[obase + (size_t)qq * EMB] = ll;
        }
    }
}

// ---------------------------------------------------------------------------
extern "C" void kernel_launch(void* const* d_in, const int* in_sizes, int n_in,
                              void* d_out, int out_size)
{
    const float* x     = (const float*)d_in[0];
    const float* W_in  = (const float*)d_in[1];
    const float* W_out = (const float*)d_in[2];
    float* out = (float*)d_out;

    __nv_bfloat16 *xhi, *xlo, *wihi, *wilo, *wohi, *wolo, *athi, *atlo;
    float *v, *cst;
    cudaGetSymbolAddress((void**)&xhi,  g_xhi);
    cudaGetSymbolAddress((void**)&xlo,  g_xlo);
    cudaGetSymbolAddress((void**)&wihi, g_wihi);
    cudaGetSymbolAddress((void**)&wilo, g_wilo);
    cudaGetSymbolAddress((void**)&wohi, g_wohi);
    cudaGetSymbolAddress((void**)&wolo, g_wolo);
    cudaGetSymbolAddress((void**)&athi, g_atthi);
    cudaGetSymbolAddress((void**)&atlo, g_attlo);
    cudaGetSymbolAddress((void**)&v,    g_v);
    cudaGetSymbolAddress((void**)&cst,  g_cst);

    const int NX = MTOT * KDIM, NW = EMB * KDIM;
    split_kernel<<<NX / (256 * 4), 256>>>(x, xhi, xlo, NX);
    split_kernel<<<NW / (256 * 4), 256>>>(W_in,  wihi, wilo, NW);
    split_kernel<<<NW / (256 * 4), 256>>>(W_out, wohi, wolo, NW);

    const dim3 ggrid(EMB / BN, MTOT / BM);   // (8, 128)
    gemm_bf16x3<<<ggrid, GTHREADS>>>(xhi, xlo, wihi, wilo, v);

    attn_const_kernel<<<dim3(BATCH, 2), 128>>>(v, cst);
    attn_kernel<<<dim3(EMB / CT, L_SEQ / QT, BATCH), 256>>>(v, athi, atlo, cst);

    gemm_bf16x3<<<ggrid, GTHREADS>>>(athi, atlo, wohi, wolo, out);
}

// round 4
// speedup vs baseline: 1.2924x; 1.1147x over previous
#include <cuda_runtime.h>
#include <cuda_bf16.h>
#include <cstdint>

#define L_SEQ 2048
#define BATCH 8
#define EMB   1024
#define KDIM  1024
#define MTOT  (BATCH * L_SEQ)   // 16384

// ---- GEMM tiling ----
#define BM 128
#define BN 128
#define BK 16
#define NCHUNK (KDIM / BK)      // 64
#define GTHREADS 256

// smem: rows padded to 48B (32B data + 16B pad) -> 20-word stride is a
// perfect bank permutation mod 32: conflict-free ldmatrix, no swizzle.
#define RSTRIDE 48
#define MAT_BYTES (BM * RSTRIDE)            // 6144
#define STAGE_BYTES (4 * MAT_BYTES)         // 24576 (Ah, Al, Bh, Bl)
#define SMEM_BYTES (2 * STAGE_BYTES)        // 49152 = 48KB exactly

// ---------------- scratch (device globals) ----------------
__device__ __nv_bfloat16 g_xhi[(size_t)MTOT * KDIM];
__device__ __nv_bfloat16 g_xlo[(size_t)MTOT * KDIM];
__device__ __nv_bfloat16 g_wihi[(size_t)EMB * KDIM];
__device__ __nv_bfloat16 g_wilo[(size_t)EMB * KDIM];
__device__ __nv_bfloat16 g_wohi[(size_t)EMB * KDIM];
__device__ __nv_bfloat16 g_wolo[(size_t)EMB * KDIM];
__device__ float         g_v[(size_t)MTOT * EMB];
__device__ __nv_bfloat16 g_atthi[(size_t)MTOT * EMB];
__device__ __nv_bfloat16 g_attlo[(size_t)MTOT * EMB];
__device__ float         g_cst[BATCH * 2 * 128];

__constant__ int c_pos[8] = {0, 1, 2, 3, 4, 0, 1, 2};
__constant__ float c_wtab[8] = {
    1.0f, 0.60653065971263342f, 0.13533528323661270f, 0.011108996538242306f,
    3.3546262790251185e-4f, 3.7266531720786709e-6f, 1.5229979744712628e-8f,
    2.2897348456455531e-11f
};

// ---------------- PTX helpers ----------------
__device__ __forceinline__ uint32_t smem_u32(const void* p) {
    uint32_t a;
    asm("{ .reg .u64 t; cvta.to.shared.u64 t, %1; cvt.u32.u64 %0, t; }" : "=r"(a) : "l"(p));
    return a;
}
__device__ __forceinline__ void cp16(uint32_t dst, const void* src) {
    asm volatile("cp.async.cg.shared.global [%0], [%1], 16;" :: "r"(dst), "l"(src) : "memory");
}
__device__ __forceinline__ void cp_commit() { asm volatile("cp.async.commit_group;" ::: "memory"); }
__device__ __forceinline__ void cp_wait0()  { asm volatile("cp.async.wait_group 0;" ::: "memory"); }

__device__ __forceinline__ void ldx4(uint32_t* r, uint32_t addr) {
    asm volatile("ldmatrix.sync.aligned.m8n8.x4.shared.b16 {%0,%1,%2,%3}, [%4];"
                 : "=r"(r[0]), "=r"(r[1]), "=r"(r[2]), "=r"(r[3]) : "r"(addr));
}
__device__ __forceinline__ void mma16816(float* c, const uint32_t* a, const uint32_t* b) {
    asm volatile("mma.sync.aligned.m16n8k16.row.col.f32.bf16.bf16.f32 "
                 "{%0,%1,%2,%3}, {%4,%5,%6,%7}, {%8,%9}, {%0,%1,%2,%3};"
                 : "+f"(c[0]), "+f"(c[1]), "+f"(c[2]), "+f"(c[3])
                 : "r"(a[0]), "r"(a[1]), "r"(a[2]), "r"(a[3]), "r"(b[0]), "r"(b[1]));
}

// ---------------------------------------------------------------------------
// bf16x3 mma.sync GEMM:  C[M,N](f32) = (Ah+Al)[M,K] · (Bh+Bl)[N,K]^T
// ---------------------------------------------------------------------------
__device__ __forceinline__ void load_chunk(
    uint32_t sb, int stage, int k0, int row0, int col0,
    const __nv_bfloat16* __restrict__ Ah, const __nv_bfloat16* __restrict__ Al,
    const __nv_bfloat16* __restrict__ Bh, const __nv_bfloat16* __restrict__ Bl, int tid)
{
    const int r = tid >> 1, c = tid & 1;                // 128 rows x 2 16B-chunks
    const uint32_t st = sb + stage * STAGE_BYTES + r * RSTRIDE + c * 16;
    const size_t ga = (size_t)(row0 + r) * KDIM + k0 + c * 8;
    const size_t gb = (size_t)(col0 + r) * KDIM + k0 + c * 8;
    cp16(st,                 Ah + ga);
    cp16(st + MAT_BYTES,     Al + ga);
    cp16(st + 2 * MAT_BYTES, Bh + gb);
    cp16(st + 3 * MAT_BYTES, Bl + gb);
    cp_commit();
}

__global__ __launch_bounds__(GTHREADS, 2)
void gemm_bf16x3(const __nv_bfloat16* __restrict__ Ah, const __nv_bfloat16* __restrict__ Al,
                 const __nv_bfloat16* __restrict__ Bh, const __nv_bfloat16* __restrict__ Bl,
                 float* __restrict__ C)
{
    __shared__ char smem[SMEM_BYTES];
    const uint32_t sb = smem_u32(smem);
    const int tid  = threadIdx.x;
    const int lane = tid & 31, wid = tid >> 5;
    const int wm = (wid & 1) * 64, wn = (wid >> 1) * 32;
    const int row0 = blockIdx.y * BM, col0 = blockIdx.x * BN;

    float acc[4][4][4];
#pragma unroll
    for (int i = 0; i < 4; ++i)
#pragma unroll
        for (int j = 0; j < 4; ++j)
#pragma unroll
            for (int k = 0; k < 4; ++k) acc[i][j][k] = 0.f;

    // per-lane ldmatrix source offsets (within a matrix block)
    const uint32_t a_off = (wm + (lane & 15)) * RSTRIDE + ((lane >> 4) << 4);
    const uint32_t b_off = (wn + (lane & 15)) * RSTRIDE + ((lane >> 4) << 4);

    load_chunk(sb, 0, 0, row0, col0, Ah, Al, Bh, Bl, tid);

    for (int i = 0; i < NCHUNK; ++i) {
        cp_wait0();              // chunk i landed (only group in flight)
        __syncthreads();         // all warps: chunk i visible AND frags of i-1 consumed

        const uint32_t st = sb + (i & 1) * STAGE_BYTES;

        // ---- fragment loads for chunk i (to registers) ----
        uint32_t ah[4][4], al[4][4];
#pragma unroll
        for (int t = 0; t < 4; ++t) {
            const uint32_t addr = st + a_off + t * (16 * RSTRIDE);
            ldx4(ah[t], addr);
            ldx4(al[t], addr + MAT_BYTES);
        }
        uint32_t bh[4][2], bl[4][2];
#pragma unroll
        for (int p = 0; p < 2; ++p) {
            const uint32_t addr = st + 2 * MAT_BYTES + b_off + p * (16 * RSTRIDE);
            uint32_t r[4];
            ldx4(r, addr);
            bh[2*p][0] = r[0]; bh[2*p][1] = r[2]; bh[2*p+1][0] = r[1]; bh[2*p+1][1] = r[3];
            ldx4(r, addr + MAT_BYTES);
            bl[2*p][0] = r[0]; bl[2*p][1] = r[2]; bl[2*p+1][0] = r[1]; bl[2*p+1][1] = r[3];
        }

        // ---- prefetch chunk i+1 into the other buffer (safe: this warp is
        // past its own frag loads; the sync above ordered everyone else's
        // reads of that buffer from iteration i-1) ----
        if (i + 1 < NCHUNK)
            load_chunk(sb, (i + 1) & 1, (i + 1) * BK, row0, col0, Ah, Al, Bh, Bl, tid);

        // ---- 48 HMMAs ----
#pragma unroll
        for (int mt = 0; mt < 4; ++mt)
#pragma unroll
            for (int nt = 0; nt < 4; ++nt) {
                mma16816(acc[mt][nt], ah[mt], bh[nt]);
                mma16816(acc[mt][nt], ah[mt], bl[nt]);
                mma16816(acc[mt][nt], al[mt], bh[nt]);
            }
    }

    // epilogue: fp32 direct store
#pragma unroll
    for (int mt = 0; mt < 4; ++mt) {
        const int m = row0 + wm + mt * 16 + (lane >> 2);
#pragma unroll
        for (int nt = 0; nt < 4; ++nt) {
            const int n = col0 + wn + nt * 8 + (lane & 3) * 2;
            *(float2*)(C + (size_t)m * EMB + n)       = make_float2(acc[mt][nt][0], acc[mt][nt][1]);
            *(float2*)(C + (size_t)(m + 8) * EMB + n) = make_float2(acc[mt][nt][2], acc[mt][nt][3]);
        }
    }
}

// ---------------------------------------------------------------------------
// fp32 -> bf16 hi/lo split
// ---------------------------------------------------------------------------
__global__ __launch_bounds__(256)
void split_kernel(const float* __restrict__ src, __nv_bfloat16* __restrict__ hi,
                  __nv_bfloat16* __restrict__ lo, int n)
{
    int i = (blockIdx.x * 256 + threadIdx.x) * 4;
    if (i >= n) return;
    float4 v = *(const float4*)(src + i);
    float f[4] = {v.x, v.y, v.z, v.w};
    __nv_bfloat16 h[4], l[4];
#pragma unroll
    for (int j = 0; j < 4; ++j) {
        h[j] = __float2bfloat16(f[j]);
        l[j] = __float2bfloat16(f[j] - __bfloat162float(h[j]));
    }
    *(uint2*)(hi + i) = *(uint2*)h;
    *(uint2*)(lo + i) = *(uint2*)l;
}

// ---------------------------------------------------------------------------
// attention: banded Gaussian conv + constant heads; emits bf16 hi/lo
// ---------------------------------------------------------------------------
__global__ void attn_const_kernel(const float* __restrict__ v, float* __restrict__ cst)
{
    const int b = blockIdx.x, which = blockIdx.y, p = threadIdx.x;
    const int h = which ? 4 : 3;
    float Z = 0.f, acc = 0.f;
#pragma unroll
    for (int j = 0; j < 8; ++j) {
        const int   k = which ? (L_SEQ - 1 - j) : j;
        const float w = c_wtab[j];
        Z += w;
        acc += w * v[((size_t)b * L_SEQ + k) * EMB + h * 128 + p];
    }
    cst[(b * 2 + which) * 128 + p] = acc / Z;
}

#define QT 16
#define CT 256
#define KT 32

__global__ __launch_bounds__(256)
void attn_kernel(const float* __restrict__ v, __nv_bfloat16* __restrict__ ahi,
                 __nv_bfloat16* __restrict__ alo, const float* __restrict__ cst)
{
    const int b = blockIdx.z, q0 = blockIdx.y * QT, c0 = blockIdx.x * CT;
    const int tid = threadIdx.x;
    __shared__ float vt[KT][CT];

    const float* vb = v + (size_t)b * L_SEQ * EMB;
#pragma unroll
    for (int i = 0; i < 8; ++i) {
        const int id = tid + i * 256;
        const int kb = id >> 6, cc = (id & 63) << 2;
        const int k  = q0 - 8 + kb;
        float4 val = make_float4(0.f, 0.f, 0.f, 0.f);
        if (k >= 0 && k < L_SEQ) val = *(const float4*)(vb + (size_t)k * EMB + c0 + cc);
        *(float4*)&vt[kb][cc] = val;
    }
    __syncthreads();

    const int c = c0 + tid, h = c >> 7, pos = c_pos[h];
    const size_t obase = ((size_t)b * L_SEQ + q0) * EMB + c;

    if (pos <= 2) {
        const int off = (pos == 0) ? 0 : (pos == 1 ? -1 : 1);
#pragma unroll
        for (int qq = 0; qq < QT; ++qq) {
            const int cen = q0 + qq + off;
            const int k0 = max(0, cen - 7), k1 = min(L_SEQ - 1, cen + 7);
            float Z = 0.f, acc = 0.f;
            for (int k = k0; k <= k1; ++k) {
                const int   d = k - cen;
                const float w = c_wtab[d < 0 ? -d : d];
                Z += w;
                acc += w * vt[k - q0 + 8][tid];
            }
            const float r = acc / Z;
            __nv_bfloat16 hh = __float2bfloat16(r);
            ahi[obase + (size_t)qq * EMB] = hh;
            alo[obase + (size_t)qq * EMB] = __float2bfloat16(r - __bfloat162float(hh));
        }
    } else {
        const float r = cst[(b * 2 + (pos == 4)) * 128 + (c & 127)];
        __nv_bfloat16 hh = __float2bfloat16(r);
        __nv_bfloat16 ll = __float2bfloat16(r - __bfloat162float(hh));
#pragma unroll
        for (int qq = 0; qq < QT; ++qq) {
            ahi[obase + (size_t)qq * EMB] = hh;
            alo[obase + (size_t)qq * EMB] = ll;
        }
    }
}

// ---------------------------------------------------------------------------
extern "C" void kernel_launch(void* const* d_in, const int* in_sizes, int n_in,
                              void* d_out, int out_size)
{
    const float* x     = (const float*)d_in[0];
    const float* W_in  = (const float*)d_in[1];
    const float* W_out = (const float*)d_in[2];
    float* out = (float*)d_out;

    __nv_bfloat16 *xhi, *xlo, *wihi, *wilo, *wohi, *wolo, *athi, *atlo;
    float *v, *cst;
    cudaGetSymbolAddress((void**)&xhi,  g_xhi);
    cudaGetSymbolAddress((void**)&xlo,  g_xlo);
    cudaGetSymbolAddress((void**)&wihi, g_wihi);
    cudaGetSymbolAddress((void**)&wilo, g_wilo);
    cudaGetSymbolAddress((void**)&wohi, g_wohi);
    cudaGetSymbolAddress((void**)&wolo, g_wolo);
    cudaGetSymbolAddress((void**)&athi, g_atthi);
    cudaGetSymbolAddress((void**)&atlo, g_attlo);
    cudaGetSymbolAddress((void**)&v,    g_v);
    cudaGetSymbolAddress((void**)&cst,  g_cst);

    const int NX = MTOT * KDIM, NW = EMB * KDIM;
    split_kernel<<<NX / (256 * 4), 256>>>(x, xhi, xlo, NX);
    split_kernel<<<NW / (256 * 4), 256>>>(W_in,  wihi, wilo, NW);
    split_kernel<<<NW / (256 * 4), 256>>>(W_out, wohi, wolo, NW);

    const dim3 ggrid(EMB / BN, MTOT / BM);   // (8, 128)
    gemm_bf16x3<<<ggrid, GTHREADS>>>(xhi, xlo, wihi, wilo, v);

    attn_const_kernel<<<dim3(BATCH, 2), 128>>>(v, cst);
    attn_kernel<<<dim3(EMB / CT, L_SEQ / QT, BATCH), 256>>>(v, athi, atlo, cst);

    gemm_bf16x3<<<ggrid, GTHREADS>>>(athi, atlo, wohi, wolo, out);
}

// round 5
// speedup vs baseline: 1.6084x; 1.2445x over previous
#include <cuda_runtime.h>
#include <cuda_bf16.h>
#include <cstdint>

#define L_SEQ 2048
#define BATCH 8
#define EMB   1024
#define KDIM  1024
#define MTOT  (BATCH * L_SEQ)   // 16384

// ---- GEMM tiling: CTA 128x256, warp 64x64 (2x4 warps), BK=16 ----
#define BM 128
#define BN 256
#define BK 16
#define NCHUNK (KDIM / BK)      // 64
#define GTHREADS 256

// smem rows padded to 48B (32B data + 16B pad): 20-word stride is a perfect
// bank permutation mod 32 -> conflict-free ldmatrix without swizzle.
#define RSTRIDE 48
#define A_HI 0
#define A_LO (BM * RSTRIDE)                  // 6144
#define B_HI (2 * BM * RSTRIDE)              // 12288
#define B_LO (B_HI + BN * RSTRIDE)           // 24576
#define STAGE_BYTES (B_LO + BN * RSTRIDE)    // 36864
#define SMEM_BYTES (2 * STAGE_BYTES)         // 73728

// ---------------- scratch (device globals) ----------------
__device__ __nv_bfloat16 g_xhi[(size_t)MTOT * KDIM];
__device__ __nv_bfloat16 g_xlo[(size_t)MTOT * KDIM];
__device__ __nv_bfloat16 g_wihi[(size_t)EMB * KDIM];
__device__ __nv_bfloat16 g_wilo[(size_t)EMB * KDIM];
__device__ __nv_bfloat16 g_wohi[(size_t)EMB * KDIM];
__device__ __nv_bfloat16 g_wolo[(size_t)EMB * KDIM];
__device__ float         g_v[(size_t)MTOT * EMB];
__device__ __nv_bfloat16 g_atthi[(size_t)MTOT * EMB];
__device__ __nv_bfloat16 g_attlo[(size_t)MTOT * EMB];
__device__ float         g_cst[BATCH * 2 * 128];

__constant__ int c_pos[8] = {0, 1, 2, 3, 4, 0, 1, 2};
__constant__ float c_wtab[8] = {
    1.0f, 0.60653065971263342f, 0.13533528323661270f, 0.011108996538242306f,
    3.3546262790251185e-4f, 3.7266531720786709e-6f, 1.5229979744712628e-8f,
    2.2897348456455531e-11f
};

// ---------------- PTX helpers ----------------
__device__ __forceinline__ uint32_t smem_u32(const void* p) {
    uint32_t a;
    asm("{ .reg .u64 t; cvta.to.shared.u64 t, %1; cvt.u32.u64 %0, t; }" : "=r"(a) : "l"(p));
    return a;
}
__device__ __forceinline__ void cp16(uint32_t dst, const void* src) {
    asm volatile("cp.async.cg.shared.global [%0], [%1], 16;" :: "r"(dst), "l"(src) : "memory");
}
__device__ __forceinline__ void cp_commit() { asm volatile("cp.async.commit_group;" ::: "memory"); }
__device__ __forceinline__ void cp_wait0()  { asm volatile("cp.async.wait_group 0;" ::: "memory"); }

__device__ __forceinline__ void ldx4(uint32_t* r, uint32_t addr) {
    asm volatile("ldmatrix.sync.aligned.m8n8.x4.shared.b16 {%0,%1,%2,%3}, [%4];"
                 : "=r"(r[0]), "=r"(r[1]), "=r"(r[2]), "=r"(r[3]) : "r"(addr));
}
__device__ __forceinline__ void mma16816(float* c, const uint32_t* a, const uint32_t* b) {
    asm volatile("mma.sync.aligned.m16n8k16.row.col.f32.bf16.bf16.f32 "
                 "{%0,%1,%2,%3}, {%4,%5,%6,%7}, {%8,%9}, {%0,%1,%2,%3};"
                 : "+f"(c[0]), "+f"(c[1]), "+f"(c[2]), "+f"(c[3])
                 : "r"(a[0]), "r"(a[1]), "r"(a[2]), "r"(a[3]), "r"(b[0]), "r"(b[1]));
}

// ---------------------------------------------------------------------------
// bf16x3 mma.sync GEMM:  C[M,N](f32) = (Ah+Al)[M,K] · (Bh+Bl)[N,K]^T
// ---------------------------------------------------------------------------
__device__ __forceinline__ void load_chunk(
    uint32_t sb, int stage, int k0, int row0, int col0,
    const __nv_bfloat16* __restrict__ Ah, const __nv_bfloat16* __restrict__ Al,
    const __nv_bfloat16* __restrict__ Bh, const __nv_bfloat16* __restrict__ Bl, int tid)
{
    const int r = tid >> 1, c = tid & 1;                // 128 rows x 2 16B-chunks
    const uint32_t st = sb + stage * STAGE_BYTES;
    const uint32_t off = r * RSTRIDE + c * 16;
    const size_t ga = (size_t)(row0 + r) * KDIM + k0 + c * 8;
    cp16(st + A_HI + off, Ah + ga);
    cp16(st + A_LO + off, Al + ga);
#pragma unroll
    for (int i = 0; i < 2; ++i) {                        // 256 B rows in 2 passes
        const int rb = r + i * 128;
        const uint32_t offb = rb * RSTRIDE + c * 16;
        const size_t gb = (size_t)(col0 + rb) * KDIM + k0 + c * 8;
        cp16(st + B_HI + offb, Bh + gb);
        cp16(st + B_LO + offb, Bl + gb);
    }
    cp_commit();
}

__global__ __launch_bounds__(GTHREADS, 1)
void gemm_bf16x3(const __nv_bfloat16* __restrict__ Ah, const __nv_bfloat16* __restrict__ Al,
                 const __nv_bfloat16* __restrict__ Bh, const __nv_bfloat16* __restrict__ Bl,
                 float* __restrict__ C)
{
    extern __shared__ char smem[];
    const uint32_t sb = smem_u32(smem);
    const int tid  = threadIdx.x;
    const int lane = tid & 31, wid = tid >> 5;
    const int wm = (wid & 1) * 64, wn = (wid >> 1) * 64;
    const int row0 = blockIdx.y * BM, col0 = blockIdx.x * BN;

    float acc[4][8][4];
#pragma unroll
    for (int i = 0; i < 4; ++i)
#pragma unroll
        for (int j = 0; j < 8; ++j)
#pragma unroll
            for (int k = 0; k < 4; ++k) acc[i][j][k] = 0.f;

    // per-lane ldmatrix source offsets (within a matrix block)
    const uint32_t a_off = (wm + (lane & 15)) * RSTRIDE + ((lane >> 4) << 4);
    const uint32_t b_off = (wn + (lane & 15)) * RSTRIDE + ((lane >> 4) << 4);

    load_chunk(sb, 0, 0, row0, col0, Ah, Al, Bh, Bl, tid);

    for (int i = 0; i < NCHUNK; ++i) {
        cp_wait0();              // chunk i landed (only group in flight)
        __syncthreads();         // chunk i visible AND frags of i-1 consumed

        const uint32_t st = sb + (i & 1) * STAGE_BYTES;

        // ---- fragment loads for chunk i ----
        uint32_t ah[4][4], al[4][4];
#pragma unroll
        for (int t = 0; t < 4; ++t) {
            const uint32_t addr = st + a_off + t * (16 * RSTRIDE);
            ldx4(ah[t], addr + A_HI);
            ldx4(al[t], addr + A_LO);
        }
        uint32_t bh[8][2], bl[8][2];
#pragma unroll
        for (int p = 0; p < 4; ++p) {
            const uint32_t addr = st + b_off + p * (16 * RSTRIDE);
            uint32_t r[4];
            ldx4(r, addr + B_HI);
            bh[2*p][0] = r[0]; bh[2*p][1] = r[2]; bh[2*p+1][0] = r[1]; bh[2*p+1][1] = r[3];
            ldx4(r, addr + B_LO);
            bl[2*p][0] = r[0]; bl[2*p][1] = r[2]; bl[2*p+1][0] = r[1]; bl[2*p+1][1] = r[3];
        }

        // ---- prefetch chunk i+1 (safe: past own frag loads; the sync above
        // ordered everyone's reads of that buffer from iteration i-1) ----
        if (i + 1 < NCHUNK)
            load_chunk(sb, (i + 1) & 1, (i + 1) * BK, row0, col0, Ah, Al, Bh, Bl, tid);

        // ---- 96 HMMAs ----
#pragma unroll
        for (int mt = 0; mt < 4; ++mt)
#pragma unroll
            for (int nt = 0; nt < 8; ++nt) {
                mma16816(acc[mt][nt], ah[mt], bh[nt]);
                mma16816(acc[mt][nt], ah[mt], bl[nt]);
                mma16816(acc[mt][nt], al[mt], bh[nt]);
            }
    }

    // epilogue: fp32 direct store
#pragma unroll
    for (int mt = 0; mt < 4; ++mt) {
        const int m = row0 + wm + mt * 16 + (lane >> 2);
#pragma unroll
        for (int nt = 0; nt < 8; ++nt) {
            const int n = col0 + wn + nt * 8 + (lane & 3) * 2;
            *(float2*)(C + (size_t)m * EMB + n)       = make_float2(acc[mt][nt][0], acc[mt][nt][1]);
            *(float2*)(C + (size_t)(m + 8) * EMB + n) = make_float2(acc[mt][nt][2], acc[mt][nt][3]);
        }
    }
}

// ---------------------------------------------------------------------------
// fp32 -> bf16 hi/lo split
// ---------------------------------------------------------------------------
__global__ __launch_bounds__(256)
void split_kernel(const float* __restrict__ src, __nv_bfloat16* __restrict__ hi,
                  __nv_bfloat16* __restrict__ lo, int n)
{
    int i = (blockIdx.x * 256 + threadIdx.x) * 4;
    if (i >= n) return;
    float4 v = *(const float4*)(src + i);
    float f[4] = {v.x, v.y, v.z, v.w};
    __nv_bfloat16 h[4], l[4];
#pragma unroll
    for (int j = 0; j < 4; ++j) {
        h[j] = __float2bfloat16(f[j]);
        l[j] = __float2bfloat16(f[j] - __bfloat162float(h[j]));
    }
    *(uint2*)(hi + i) = *(uint2*)h;
    *(uint2*)(lo + i) = *(uint2*)l;
}

// ---------------------------------------------------------------------------
// attention: banded Gaussian conv + constant heads; emits bf16 hi/lo
// ---------------------------------------------------------------------------
__global__ void attn_const_kernel(const float* __restrict__ v, float* __restrict__ cst)
{
    const int b = blockIdx.x, which = blockIdx.y, p = threadIdx.x;
    const int h = which ? 4 : 3;
    float Z = 0.f, acc = 0.f;
#pragma unroll
    for (int j = 0; j < 8; ++j) {
        const int   k = which ? (L_SEQ - 1 - j) : j;
        const float w = c_wtab[j];
        Z += w;
        acc += w * v[((size_t)b * L_SEQ + k) * EMB + h * 128 + p];
    }
    cst[(b * 2 + which) * 128 + p] = acc / Z;
}

#define QT 16
#define CT 256
#define KT 32

__global__ __launch_bounds__(256)
void attn_kernel(const float* __restrict__ v, __nv_bfloat16* __restrict__ ahi,
                 __nv_bfloat16* __restrict__ alo, const float* __restrict__ cst)
{
    const int b = blockIdx.z, q0 = blockIdx.y * QT, c0 = blockIdx.x * CT;
    const int tid = threadIdx.x;
    __shared__ float vt[KT][CT];

    const float* vb = v + (size_t)b * L_SEQ * EMB;
#pragma unroll
    for (int i = 0; i < 8; ++i) {
        const int id = tid + i * 256;
        const int kb = id >> 6, cc = (id & 63) << 2;
        const int k  = q0 - 8 + kb;
        float4 val = make_float4(0.f, 0.f, 0.f, 0.f);
        if (k >= 0 && k < L_SEQ) val = *(const float4*)(vb + (size_t)k * EMB + c0 + cc);
        *(float4*)&vt[kb][cc] = val;
    }
    __syncthreads();

    const int c = c0 + tid, h = c >> 7, pos = c_pos[h];
    const size_t obase = ((size_t)b * L_SEQ + q0) * EMB + c;

    if (pos <= 2) {
        const int off = (pos == 0) ? 0 : (pos == 1 ? -1 : 1);
#pragma unroll
        for (int qq = 0; qq < QT; ++qq) {
            const int cen = q0 + qq + off;
            const int k0 = max(0, cen - 7), k1 = min(L_SEQ - 1, cen + 7);
            float Z = 0.f, acc = 0.f;
            for (int k = k0; k <= k1; ++k) {
                const int   d = k - cen;
                const float w = c_wtab[d < 0 ? -d : d];
                Z += w;
                acc += w * vt[k - q0 + 8][tid];
            }
            const float r = acc / Z;
            __nv_bfloat16 hh = __float2bfloat16(r);
            ahi[obase + (size_t)qq * EMB] = hh;
            alo[obase + (size_t)qq * EMB] = __float2bfloat16(r - __bfloat162float(hh));
        }
    } else {
        const float r = cst[(b * 2 + (pos == 4)) * 128 + (c & 127)];
        __nv_bfloat16 hh = __float2bfloat16(r);
        __nv_bfloat16 ll = __float2bfloat16(r - __bfloat162float(hh));
#pragma unroll
        for (int qq = 0; qq < QT; ++qq) {
            ahi[obase + (size_t)qq * EMB] = hh;
            alo[obase + (size_t)qq * EMB] = ll;
        }
    }
}

// ---------------------------------------------------------------------------
extern "C" void kernel_launch(void* const* d_in, const int* in_sizes, int n_in,
                              void* d_out, int out_size)
{
    const float* x     = (const float*)d_in[0];
    const float* W_in  = (const float*)d_in[1];
    const float* W_out = (const float*)d_in[2];
    float* out = (float*)d_out;

    __nv_bfloat16 *xhi, *xlo, *wihi, *wilo, *wohi, *wolo, *athi, *atlo;
    float *v, *cst;
    cudaGetSymbolAddress((void**)&xhi,  g_xhi);
    cudaGetSymbolAddress((void**)&xlo,  g_xlo);
    cudaGetSymbolAddress((void**)&wihi, g_wihi);
    cudaGetSymbolAddress((void**)&wilo, g_wilo);
    cudaGetSymbolAddress((void**)&wohi, g_wohi);
    cudaGetSymbolAddress((void**)&wolo, g_wolo);
    cudaGetSymbolAddress((void**)&athi, g_atthi);
    cudaGetSymbolAddress((void**)&atlo, g_attlo);
    cudaGetSymbolAddress((void**)&v,    g_v);
    cudaGetSymbolAddress((void**)&cst,  g_cst);

    static bool attr_done = false;
    if (!attr_done) {
        cudaFuncSetAttribute(gemm_bf16x3, cudaFuncAttributeMaxDynamicSharedMemorySize, SMEM_BYTES);
        attr_done = true;
    }

    const int NX = MTOT * KDIM, NW = EMB * KDIM;
    split_kernel<<<NX / (256 * 4), 256>>>(x, xhi, xlo, NX);
    split_kernel<<<NW / (256 * 4), 256>>>(W_in,  wihi, wilo, NW);
    split_kernel<<<NW / (256 * 4), 256>>>(W_out, wohi, wolo, NW);

    const dim3 ggrid(EMB / BN, MTOT / BM);   // (4, 128)
    gemm_bf16x3<<<ggrid, GTHREADS, SMEM_BYTES>>>(xhi, xlo, wihi, wilo, v);

    attn_const_kernel<<<dim3(BATCH, 2), 128>>>(v, cst);
    attn_kernel<<<dim3(EMB / CT, L_SEQ / QT, BATCH), 256>>>(v, athi, atlo, cst);

    gemm_bf16x3<<<ggrid, GTHREADS, SMEM_BYTES>>>(athi, atlo, wohi, wolo, out);
}

// round 6
// speedup vs baseline: 1.6571x; 1.0303x over previous
#include <cuda_runtime.h>
#include <cuda_bf16.h>
#include <cstdint>

#define L_SEQ 2048
#define BATCH 8
#define EMB   1024
#define KDIM  1024
#define MTOT  (BATCH * L_SEQ)   // 16384

// ---- GEMM tiling: CTA 128x128, 4 warps (2x2), warp tile 64x64, BK=16 ----
#define BM 128
#define BN 128
#define BK 16
#define NCHUNK (KDIM / BK)      // 64
#define GTHREADS 128

// smem rows padded to 48B (32B data + 16B pad): 20-word stride is a perfect
// bank permutation mod 32 -> conflict-free ldmatrix without swizzle.
#define RSTRIDE 48
#define A_HI 0
#define A_LO (BM * RSTRIDE)                  // 6144
#define B_HI (2 * BM * RSTRIDE)              // 12288
#define B_LO (B_HI + BN * RSTRIDE)           // 18432
#define STAGE_BYTES (B_LO + BN * RSTRIDE)    // 24576
#define SMEM_BYTES (2 * STAGE_BYTES)         // 49152 = 48KB

// ---------------- scratch (device globals) ----------------
__device__ __nv_bfloat16 g_xhi[(size_t)MTOT * KDIM];
__device__ __nv_bfloat16 g_xlo[(size_t)MTOT * KDIM];
__device__ __nv_bfloat16 g_wihi[(size_t)EMB * KDIM];
__device__ __nv_bfloat16 g_wilo[(size_t)EMB * KDIM];
__device__ __nv_bfloat16 g_wohi[(size_t)EMB * KDIM];
__device__ __nv_bfloat16 g_wolo[(size_t)EMB * KDIM];
__device__ float         g_v[(size_t)MTOT * EMB];
__device__ __nv_bfloat16 g_atthi[(size_t)MTOT * EMB];
__device__ __nv_bfloat16 g_attlo[(size_t)MTOT * EMB];
__device__ float         g_cst[BATCH * 2 * 128];

__constant__ int c_pos[8] = {0, 1, 2, 3, 4, 0, 1, 2};
__constant__ float c_wtab[8] = {
    1.0f, 0.60653065971263342f, 0.13533528323661270f, 0.011108996538242306f,
    3.3546262790251185e-4f, 3.7266531720786709e-6f, 1.5229979744712628e-8f,
    2.2897348456455531e-11f
};

// ---------------- PTX helpers ----------------
__device__ __forceinline__ uint32_t smem_u32(const void* p) {
    uint32_t a;
    asm("{ .reg .u64 t; cvta.to.shared.u64 t, %1; cvt.u32.u64 %0, t; }" : "=r"(a) : "l"(p));
    return a;
}
__device__ __forceinline__ void cp16(uint32_t dst, const void* src) {
    asm volatile("cp.async.cg.shared.global [%0], [%1], 16;" :: "r"(dst), "l"(src) : "memory");
}
__device__ __forceinline__ void cp_commit() { asm volatile("cp.async.commit_group;" ::: "memory"); }
__device__ __forceinline__ void cp_wait0()  { asm volatile("cp.async.wait_group 0;" ::: "memory"); }

__device__ __forceinline__ void ldx4(uint32_t* r, uint32_t addr) {
    asm volatile("ldmatrix.sync.aligned.m8n8.x4.shared.b16 {%0,%1,%2,%3}, [%4];"
                 : "=r"(r[0]), "=r"(r[1]), "=r"(r[2]), "=r"(r[3]) : "r"(addr));
}
__device__ __forceinline__ void mma16816(float* c, const uint32_t* a, const uint32_t* b) {
    asm volatile("mma.sync.aligned.m16n8k16.row.col.f32.bf16.bf16.f32 "
                 "{%0,%1,%2,%3}, {%4,%5,%6,%7}, {%8,%9}, {%0,%1,%2,%3};"
                 : "+f"(c[0]), "+f"(c[1]), "+f"(c[2]), "+f"(c[3])
                 : "r"(a[0]), "r"(a[1]), "r"(a[2]), "r"(a[3]), "r"(b[0]), "r"(b[1]));
}

// ---------------------------------------------------------------------------
// bf16x3 mma.sync GEMM:  C[M,N](f32) = (Ah+Al)[M,K] · (Bh+Bl)[N,K]^T
// ---------------------------------------------------------------------------
__device__ __forceinline__ void load_chunk(
    uint32_t sb, int stage, int k0, int row0, int col0,
    const __nv_bfloat16* __restrict__ Ah, const __nv_bfloat16* __restrict__ Al,
    const __nv_bfloat16* __restrict__ Bh, const __nv_bfloat16* __restrict__ Bl, int tid)
{
    // 128 threads: each thread owns one row (A and B), 2x16B per matrix
    const uint32_t st  = sb + stage * STAGE_BYTES;
    const uint32_t off = tid * RSTRIDE;
    const size_t ga = (size_t)(row0 + tid) * KDIM + k0;
    const size_t gb = (size_t)(col0 + tid) * KDIM + k0;
    cp16(st + A_HI + off,      Ah + ga);
    cp16(st + A_HI + off + 16, Ah + ga + 8);
    cp16(st + A_LO + off,      Al + ga);
    cp16(st + A_LO + off + 16, Al + ga + 8);
    cp16(st + B_HI + off,      Bh + gb);
    cp16(st + B_HI + off + 16, Bh + gb + 8);
    cp16(st + B_LO + off,      Bl + gb);
    cp16(st + B_LO + off + 16, Bl + gb + 8);
    cp_commit();
}

__global__ __launch_bounds__(GTHREADS, 2)
void gemm_bf16x3(const __nv_bfloat16* __restrict__ Ah, const __nv_bfloat16* __restrict__ Al,
                 const __nv_bfloat16* __restrict__ Bh, const __nv_bfloat16* __restrict__ Bl,
                 float* __restrict__ C)
{
    __shared__ char smem[SMEM_BYTES];
    const uint32_t sb = smem_u32(smem);
    const int tid  = threadIdx.x;
    const int lane = tid & 31, wid = tid >> 5;
    const int wm = (wid & 1) * 64, wn = (wid >> 1) * 64;
    const int row0 = blockIdx.y * BM, col0 = blockIdx.x * BN;

    float acc[4][8][4];
#pragma unroll
    for (int i = 0; i < 4; ++i)
#pragma unroll
        for (int j = 0; j < 8; ++j)
#pragma unroll
            for (int k = 0; k < 4; ++k) acc[i][j][k] = 0.f;

    // per-lane ldmatrix source offsets (within a matrix block)
    const uint32_t a_off = (wm + (lane & 15)) * RSTRIDE + ((lane >> 4) << 4);
    const uint32_t b_off = (wn + (lane & 15)) * RSTRIDE + ((lane >> 4) << 4);

    load_chunk(sb, 0, 0, row0, col0, Ah, Al, Bh, Bl, tid);

    for (int i = 0; i < NCHUNK; ++i) {
        cp_wait0();              // chunk i landed (only group in flight)
        __syncthreads();         // chunk i visible AND frags of i-1 consumed

        const uint32_t st = sb + (i & 1) * STAGE_BYTES;

        // ---- fragment loads for chunk i ----
        uint32_t ah[4][4], al[4][4];
#pragma unroll
        for (int t = 0; t < 4; ++t) {
            const uint32_t addr = st + a_off + t * (16 * RSTRIDE);
            ldx4(ah[t], addr + A_HI);
            ldx4(al[t], addr + A_LO);
        }
        uint32_t bh[8][2], bl[8][2];
#pragma unroll
        for (int p = 0; p < 4; ++p) {
            const uint32_t addr = st + b_off + p * (16 * RSTRIDE);
            uint32_t r[4];
            ldx4(r, addr + B_HI);
            bh[2*p][0] = r[0]; bh[2*p][1] = r[2]; bh[2*p+1][0] = r[1]; bh[2*p+1][1] = r[3];
            ldx4(r, addr + B_LO);
            bl[2*p][0] = r[0]; bl[2*p][1] = r[2]; bl[2*p+1][0] = r[1]; bl[2*p+1][1] = r[3];
        }

        // ---- prefetch chunk i+1 (safe: past own frag loads; the sync above
        // ordered everyone's reads of that buffer from iteration i-1) ----
        if (i + 1 < NCHUNK)
            load_chunk(sb, (i + 1) & 1, (i + 1) * BK, row0, col0, Ah, Al, Bh, Bl, tid);

        // ---- 96 HMMAs ----
#pragma unroll
        for (int mt = 0; mt < 4; ++mt)
#pragma unroll
            for (int nt = 0; nt < 8; ++nt) {
                mma16816(acc[mt][nt], ah[mt], bh[nt]);
                mma16816(acc[mt][nt], ah[mt], bl[nt]);
                mma16816(acc[mt][nt], al[mt], bh[nt]);
            }
    }

    // epilogue: fp32 direct store
#pragma unroll
    for (int mt = 0; mt < 4; ++mt) {
        const int m = row0 + wm + mt * 16 + (lane >> 2);
#pragma unroll
        for (int nt = 0; nt < 8; ++nt) {
            const int n = col0 + wn + nt * 8 + (lane & 3) * 2;
            *(float2*)(C + (size_t)m * EMB + n)       = make_float2(acc[mt][nt][0], acc[mt][nt][1]);
            *(float2*)(C + (size_t)(m + 8) * EMB + n) = make_float2(acc[mt][nt][2], acc[mt][nt][3]);
        }
    }
}

// ---------------------------------------------------------------------------
// fp32 -> bf16 hi/lo split
// ---------------------------------------------------------------------------
__global__ __launch_bounds__(256)
void split_kernel(const float* __restrict__ src, __nv_bfloat16* __restrict__ hi,
                  __nv_bfloat16* __restrict__ lo, int n)
{
    int i = (blockIdx.x * 256 + threadIdx.x) * 4;
    if (i >= n) return;
    float4 v = *(const float4*)(src + i);
    float f[4] = {v.x, v.y, v.z, v.w};
    __nv_bfloat16 h[4], l[4];
#pragma unroll
    for (int j = 0; j < 4; ++j) {
        h[j] = __float2bfloat16(f[j]);
        l[j] = __float2bfloat16(f[j] - __bfloat162float(h[j]));
    }
    *(uint2*)(hi + i) = *(uint2*)h;
    *(uint2*)(lo + i) = *(uint2*)l;
}

// ---------------------------------------------------------------------------
// attention: banded Gaussian conv + constant heads; emits bf16 hi/lo
// ---------------------------------------------------------------------------
__global__ void attn_const_kernel(const float* __restrict__ v, float* __restrict__ cst)
{
    const int b = blockIdx.x, which = blockIdx.y, p = threadIdx.x;
    const int h = which ? 4 : 3;
    float Z = 0.f, acc = 0.f;
#pragma unroll
    for (int j = 0; j < 8; ++j) {
        const int   k = which ? (L_SEQ - 1 - j) : j;
        const float w = c_wtab[j];
        Z += w;
        acc += w * v[((size_t)b * L_SEQ + k) * EMB + h * 128 + p];
    }
    cst[(b * 2 + which) * 128 + p] = acc / Z;
}

#define QT 16
#define CT 256
#define KT 32

__global__ __launch_bounds__(256)
void attn_kernel(const float* __restrict__ v, __nv_bfloat16* __restrict__ ahi,
                 __nv_bfloat16* __restrict__ alo, const float* __restrict__ cst)
{
    const int b = blockIdx.z, q0 = blockIdx.y * QT, c0 = blockIdx.x * CT;
    const int tid = threadIdx.x;
    __shared__ float vt[KT][CT];

    const float* vb = v + (size_t)b * L_SEQ * EMB;
#pragma unroll
    for (int i = 0; i < 8; ++i) {
        const int id = tid + i * 256;
        const int kb = id >> 6, cc = (id & 63) << 2;
        const int k  = q0 - 8 + kb;
        float4 val = make_float4(0.f, 0.f, 0.f, 0.f);
        if (k >= 0 && k < L_SEQ) val = *(const float4*)(vb + (size_t)k * EMB + c0 + cc);
        *(float4*)&vt[kb][cc] = val;
    }
    __syncthreads();

    const int c = c0 + tid, h = c >> 7, pos = c_pos[h];
    const size_t obase = ((size_t)b * L_SEQ + q0) * EMB + c;

    if (pos <= 2) {
        const int off = (pos == 0) ? 0 : (pos == 1 ? -1 : 1);
#pragma unroll
        for (int qq = 0; qq < QT; ++qq) {
            const int cen = q0 + qq + off;
            const int k0 = max(0, cen - 7), k1 = min(L_SEQ - 1, cen + 7);
            float Z = 0.f, acc = 0.f;
            for (int k = k0; k <= k1; ++k) {
                const int   d = k - cen;
                const float w = c_wtab[d < 0 ? -d : d];
                Z += w;
                acc += w * vt[k - q0 + 8][tid];
            }
            const float r = acc / Z;
            __nv_bfloat16 hh = __float2bfloat16(r);
            ahi[obase + (size_t)qq * EMB] = hh;
            alo[obase + (size_t)qq * EMB] = __float2bfloat16(r - __bfloat162float(hh));
        }
    } else {
        const float r = cst[(b * 2 + (pos == 4)) * 128 + (c & 127)];
        __nv_bfloat16 hh = __float2bfloat16(r);
        __nv_bfloat16 ll = __float2bfloat16(r - __bfloat162float(hh));
#pragma unroll
        for (int qq = 0; qq < QT; ++qq) {
            ahi[obase + (size_t)qq * EMB] = hh;
            alo[obase + (size_t)qq * EMB] = ll;
        }
    }
}

// ---------------------------------------------------------------------------
extern "C" void kernel_launch(void* const* d_in, const int* in_sizes, int n_in,
                              void* d_out, int out_size)
{
    const float* x     = (const float*)d_in[0];
    const float* W_in  = (const float*)d_in[1];
    const float* W_out = (const float*)d_in[2];
    float* out = (float*)d_out;

    __nv_bfloat16 *xhi, *xlo, *wihi, *wilo, *wohi, *wolo, *athi, *atlo;
    float *v, *cst;
    cudaGetSymbolAddress((void**)&xhi,  g_xhi);
    cudaGetSymbolAddress((void**)&xlo,  g_xlo);
    cudaGetSymbolAddress((void**)&wihi, g_wihi);
    cudaGetSymbolAddress((void**)&wilo, g_wilo);
    cudaGetSymbolAddress((void**)&wohi, g_wohi);
    cudaGetSymbolAddress((void**)&wolo, g_wolo);
    cudaGetSymbolAddress((void**)&athi, g_atthi);
    cudaGetSymbolAddress((void**)&atlo, g_attlo);
    cudaGetSymbolAddress((void**)&v,    g_v);
    cudaGetSymbolAddress((void**)&cst,  g_cst);

    const int NX = MTOT * KDIM, NW = EMB * KDIM;
    split_kernel<<<NX / (256 * 4), 256>>>(x, xhi, xlo, NX);
    split_kernel<<<NW / (256 * 4), 256>>>(W_in,  wihi, wilo, NW);
    split_kernel<<<NW / (256 * 4), 256>>>(W_out, wohi, wolo, NW);

    const dim3 ggrid(EMB / BN, MTOT / BM);   // (8, 128)
    gemm_bf16x3<<<ggrid, GTHREADS>>>(xhi, xlo, wihi, wilo, v);

    attn_const_kernel<<<dim3(BATCH, 2), 128>>>(v, cst);
    attn_kernel<<<dim3(EMB / CT, L_SEQ / QT, BATCH), 256>>>(v, athi, atlo, cst);

    gemm_bf16x3<<<ggrid, GTHREADS>>>(athi, atlo, wohi, wolo, out);
}